// round 5
// baseline (speedup 1.0000x reference)
#include <cuda_runtime.h>
#include <math.h>

#define NQ   32768
#define NS   65536
#define KNN  30
#define G    64
#define NC   (G * G * G)
#define BOUND 5.2f
#define FINF  3.4e38f

// ---------------------------------------------------------------------------
// Scratch (static device globals — no allocation at launch time)
// ---------------------------------------------------------------------------
__device__ int    g_cnt_s[NC];
__device__ int    g_start_s[NC + 1];
__device__ int    g_cur_s[NC];
__device__ int    g_cnt_q[NC];
__device__ int    g_start_q[NC + 1];
__device__ int    g_cur_q[NC];
__device__ float4 g_src[NS];          // sorted-by-cell sources, .w = orig idx
__device__ float4 g_qry[NQ];          // sorted-by-cell queries, .w = orig idx
__device__ int    g_idx[NQ * KNN];    // per ORIGINAL query
__device__ float  g_h[NQ];

__device__ __forceinline__ int cellc(float v) {
    int c = (int)floorf((v + BOUND) * ((float)G / (2.0f * BOUND)));
    return min(max(c, 0), G - 1);
}

// ---------------------------------------------------------------------------
// Build pipeline: zero -> histogram -> scan -> scatter (for sources & queries)
// ---------------------------------------------------------------------------
__global__ void zero_kernel() {
    int i = blockIdx.x * blockDim.x + threadIdx.x;
    if (i < NC) g_cnt_s[i] = 0;
    else if (i < 2 * NC) g_cnt_q[i - NC] = 0;
}

__global__ void hist_kernel(const float* __restrict__ p, int n, int isq) {
    int i = blockIdx.x * blockDim.x + threadIdx.x;
    if (i >= n) return;
    int cid = (cellc(p[3 * i + 2]) * G + cellc(p[3 * i + 1])) * G + cellc(p[3 * i]);
    atomicAdd(isq ? &g_cnt_q[cid] : &g_cnt_s[cid], 1);
}

__global__ __launch_bounds__(1024) void scan_kernel(int isq) {
    __shared__ int part[1024];
    const int* cnt = isq ? g_cnt_q : g_cnt_s;
    int* start     = isq ? g_start_q : g_start_s;
    int* cur       = isq ? g_cur_q : g_cur_s;
    const int tid = threadIdx.x;
    const int per = NC / 1024;      // 256
    const int base = tid * per;

    int ssum = 0;
    for (int i = 0; i < per; ++i) ssum += cnt[base + i];
    part[tid] = ssum;
    __syncthreads();
    for (int off = 1; off < 1024; off <<= 1) {
        int v = (tid >= off) ? part[tid - off] : 0;
        __syncthreads();
        part[tid] += v;
        __syncthreads();
    }
    int run = (tid == 0) ? 0 : part[tid - 1];
    for (int i = 0; i < per; ++i) {
        start[base + i] = run;
        cur[base + i]   = run;
        run += cnt[base + i];
    }
    if (tid == 1023) start[NC] = run;
}

__global__ void scatter_kernel(const float* __restrict__ p, int n, int isq) {
    int i = blockIdx.x * blockDim.x + threadIdx.x;
    if (i >= n) return;
    float x = p[3 * i], y = p[3 * i + 1], z = p[3 * i + 2];
    int cid = (cellc(z) * G + cellc(y)) * G + cellc(x);
    int pos = atomicAdd(isq ? &g_cur_q[cid] : &g_cur_s[cid], 1);
    float4 v = make_float4(x, y, z, __int_as_float(i));
    if (isq) g_qry[pos] = v; else g_src[pos] = v;
}

// ---------------------------------------------------------------------------
// Grid KNN: one thread per (cell-sorted) query. Ring expansion with exact
// covered-ball termination in clamped cell space.
// ---------------------------------------------------------------------------
__global__ __launch_bounds__(256) void knn_grid_kernel() {
    const int t = blockIdx.x * 256 + threadIdx.x;
    const float4 qv = g_qry[t];
    const float qx = qv.x, qy = qv.y, qz = qv.z;
    const int orig = __float_as_int(qv.w);

    const int qcx = cellc(qx), qcy = cellc(qy), qcz = cellc(qz);

    float bd[KNN];
    int   bi[KNN];
#pragma unroll
    for (int i = 0; i < KNN; ++i) { bd[i] = FINF; bi[i] = 0; }
    float worst = FINF;

    int plox = 1, phix = 0, ploy = 1, phiy = 0, ploz = 1, phiz = 0;   // empty

    for (int r = 0; ; ++r) {
        const int lox = max(qcx - r, 0), hix = min(qcx + r, G - 1);
        const int loy = max(qcy - r, 0), hiy = min(qcy + r, G - 1);
        const int loz = max(qcz - r, 0), hiz = min(qcz + r, G - 1);

        for (int z = loz; z <= hiz; ++z) {
            const bool zin = (z >= ploz && z <= phiz);
            for (int y = loy; y <= hiy; ++y) {
                const bool yin = zin && (y >= ploy && y <= phiy);
                const int rowbase = (z * G + y) * G;
                for (int x = lox; x <= hix; ++x) {
                    if (yin && x >= plox && x <= phix) continue;   // already scanned
                    const int cid = rowbase + x;
                    const int a = g_start_s[cid];
                    const int b = g_start_s[cid + 1];
                    for (int i = a; i < b; ++i) {
                        const float4 p = g_src[i];
                        const float dx = qx - p.x, dy = qy - p.y, dz = qz - p.z;
                        const float d2 = fmaf(dx, dx, fmaf(dy, dy, dz * dz));
                        if (d2 < worst) {
                            float dd = d2;
                            int   ii = __float_as_int(p.w);
#pragma unroll
                            for (int k = 0; k < KNN; ++k) {
                                if (dd < bd[k]) {
                                    const float tf = bd[k]; bd[k] = dd; dd = tf;
                                    const int   ti = bi[k]; bi[k] = ii; ii = ti;
                                }
                            }
                            worst = bd[KNN - 1];
                        }
                    }
                }
            }
        }

        const bool full = (lox == 0 && hix == G - 1 && loy == 0 && hiy == G - 1 &&
                           loz == 0 && hiz == G - 1);
        if (worst < FINF) {
            const float rad = sqrtf(worst);
            if (cellc(qx - rad) >= lox && cellc(qx + rad) <= hix &&
                cellc(qy - rad) >= loy && cellc(qy + rad) <= hiy &&
                cellc(qz - rad) >= loz && cellc(qz + rad) <= hiz)
                break;   // 30-NN ball fully inside scanned cube -> exact
        }
        if (full) break;
        plox = lox; phix = hix; ploy = loy; phiy = hiy; ploz = loz; phiz = hiz;
    }

    float hs = 0.0f;
#pragma unroll
    for (int i = 0; i < KNN; ++i) hs += sqrtf(fmaxf(bd[i], 0.0f));
    g_h[orig] = hs * (1.0f / (float)KNN) + 1e-8f;
#pragma unroll
    for (int i = 0; i < KNN; ++i) g_idx[orig * KNN + i] = bi[i];
}

// ---------------------------------------------------------------------------
// RIMLS iterations, one warp per query (unchanged from passing R1 kernel).
// ---------------------------------------------------------------------------
__global__ __launch_bounds__(256) void rimls_kernel(const float* __restrict__ q,
                                                    const float* __restrict__ s,
                                                    const float* __restrict__ nrm,
                                                    float* __restrict__ out) {
    const int warp = (blockIdx.x * 256 + threadIdx.x) >> 5;
    const int lane = threadIdx.x & 31;
    if (warp >= NQ) return;

    const float qx = q[3 * warp + 0];
    const float qy = q[3 * warp + 1];
    const float qz = q[3 * warp + 2];
    const float h  = g_h[warp];
    const float inv_h2 = 1.0f / (h * h);

    const bool act = (lane < KNN);
    float nx = 0.f, ny = 0.f, nz = 0.f;
    float fx = 0.f, phi = 0.f;
    float gpx = 0.f, gpy = 0.f, gpz = 0.f;

    if (act) {
        const int id = g_idx[warp * KNN + lane];
        const float sx = s[3 * id + 0];
        const float sy = s[3 * id + 1];
        const float sz = s[3 * id + 2];
        float ax = nrm[3 * id + 0];
        float ay = nrm[3 * id + 1];
        float az = nrm[3 * id + 2];
        const float nn  = sqrtf(ax * ax + ay * ay + az * az);
        const float inv = 1.0f / fmaxf(nn, 1e-8f);
        nx = ax * inv; ny = ay * inv; nz = az * inv;

        const float px = qx - sx, py = qy - sy, pz = qz - sz;
        fx = px * nx + py * ny + pz * nz;
        const float r2 = px * px + py * py + pz * pz;
        const float t  = fmaxf(1.0f - r2 * inv_h2, 0.0f);
        const float t2 = t * t;
        phi = t2 * t2;
        const float gc = -8.0f * inv_h2 * t * t2;
        gpx = gc * px; gpy = gc * py; gpz = gc * pz;
    }

    float f = 0.f, gx = 0.f, gy = 0.f, gz = 0.f;
    bool done = false;
    const float inv_sn2 = 1.0f / (0.8f * 0.8f);

    for (int it = 0; it < 3; ++it) {
        float alpha;
        if (it == 0) {
            alpha = 1.0f;
        } else {
            const float dx = nx - gx, dy = ny - gy, dz = nz - gz;
            alpha = expf(-(dx * dx + dy * dy + dz * dz) * inv_sn2);
        }
        const float w   = alpha * phi;
        const float gwx = alpha * gpx;
        const float gwy = alpha * gpy;
        const float gwz = alpha * gpz;

        float r0 = w;
        float r1 = w * fx;
        float m0 = fmaf(gwx, fx, w * nx);
        float m1 = fmaf(gwy, fx, w * ny);
        float m2 = fmaf(gwz, fx, w * nz);
        float s0 = gwx, s1 = gwy, s2 = gwz;

#pragma unroll
        for (int off = 16; off; off >>= 1) {
            r0 += __shfl_xor_sync(0xffffffffu, r0, off);
            r1 += __shfl_xor_sync(0xffffffffu, r1, off);
            m0 += __shfl_xor_sync(0xffffffffu, m0, off);
            m1 += __shfl_xor_sync(0xffffffffu, m1, off);
            m2 += __shfl_xor_sync(0xffffffffu, m2, off);
            s0 += __shfl_xor_sync(0xffffffffu, s0, off);
            s1 += __shfl_xor_sync(0xffffffffu, s1, off);
            s2 += __shfl_xor_sync(0xffffffffu, s2, off);
        }

        const float sw    = r0 + 1e-8f;
        const float f_new = r1 / sw;
        const float gnx   = (m0 - f_new * s0) / sw;
        const float gny   = (m1 - f_new * s1) / sw;
        const float gnz   = (m2 - f_new * s2) / sw;

        const float delta = fabsf(f_new - f);
        if (!done) { f = f_new; gx = gnx; gy = gny; gz = gnz; }
        done = done || (delta < 1e-3f);
    }

    if (lane == 0) {
        out[warp] = f;
        out[NQ + 3 * warp + 0] = gx;
        out[NQ + 3 * warp + 1] = gy;
        out[NQ + 3 * warp + 2] = gz;
    }
}

// ---------------------------------------------------------------------------
extern "C" void kernel_launch(void* const* d_in, const int* in_sizes, int n_in,
                              void* d_out, int out_size) {
    const float* q = (const float*)d_in[0];   // query_points   [32768,3]
    const float* s = (const float*)d_in[1];   // source_vertices[65536,3]
    const float* n = (const float*)d_in[2];   // source_normals [65536,3]
    float* out = (float*)d_out;

    zero_kernel<<<(2 * NC + 255) / 256, 256>>>();
    hist_kernel<<<(NS + 255) / 256, 256>>>(s, NS, 0);
    hist_kernel<<<(NQ + 255) / 256, 256>>>(q, NQ, 1);
    scan_kernel<<<1, 1024>>>(0);
    scan_kernel<<<1, 1024>>>(1);
    scatter_kernel<<<(NS + 255) / 256, 256>>>(s, NS, 0);
    scatter_kernel<<<(NQ + 255) / 256, 256>>>(q, NQ, 1);
    knn_grid_kernel<<<NQ / 256, 256>>>();
    rimls_kernel<<<NQ / 8, 256>>>(q, s, n, out);
}